// round 4
// baseline (speedup 1.0000x reference)
#include <cuda_runtime.h>
#include <cstdint>

#define BB 4
#define NN 65536
#define QQ 400
#define CC 20
#define MM 64
#define CH 512                   // rows per sort chunk
#define NCHUNK (NN / CH)         // 128 chunks per batch

// ---------------- device scratch (no mallocs allowed) ----------------
__device__ float g_accX[BB*MM*QQ];     // sum x per (b,m,q)
__device__ float g_accG[BB*MM*QQ];     // sum (sigmoid-0.5)-ish per (b,m,q)
__device__ float g_accL[BB*QQ];        // sum log2(sigma(-x)) per (b,q)  [negative]
__device__ int   g_segmax[BB*MM];      // inst_seg
__device__ int   g_mstart[BB*MM];      // per-batch start offset of each m
__device__ int   g_hist[BB*MM*NCHUNK]; // [b][m][chunk] counts -> offsets
__device__ int   g_smaxc[BB*MM*NCHUNK];// [b][m][chunk] per-chunk seg max
__device__ unsigned short g_sorder[BB*NN]; // point indices grouped by m

// ---------------- fast approx ops ----------------
__device__ __forceinline__ float tanha(float x){ float r; asm("tanh.approx.f32 %0, %1;" : "=f"(r) : "f"(x)); return r; }
__device__ __forceinline__ float lg2a(float x){ float r; asm("lg2.approx.f32 %0, %1;" : "=f"(r) : "f"(x)); return r; }

// ---------------- sort pass 1: per-chunk histogram + segmax + zero accs ------
__global__ void khist(const int* __restrict__ inst, const int* __restrict__ seg) {
    const int b  = blockIdx.y;
    const int ch = blockIdx.x;
    __shared__ int h[MM];
    __shared__ int smax[MM];
    if (threadIdx.x < MM) { h[threadIdx.x] = 0; smax[threadIdx.x] = 0; }
    __syncthreads();

    // fused zeroing of accumulators (512 blocks x 256 thr = 131072 >= 102400)
    const int gtid = (b * NCHUNK + ch) * 256 + threadIdx.x;
    if (gtid < BB*MM*QQ) { g_accX[gtid] = 0.f; g_accG[gtid] = 0.f; }
    if (gtid < BB*QQ) g_accL[gtid] = 0.f;

    const int base = b * NN + ch * CH;
    #pragma unroll
    for (int k = 0; k < CH / 256; k++) {
        int n = base + threadIdx.x + k * 256;
        int m = __ldg(inst + n);
        int s = __ldg(seg + n);
        atomicAdd(&h[m], 1);
        atomicMax(&smax[m], s);
    }
    __syncthreads();
    if (threadIdx.x < MM) {
        g_hist [(b * MM + threadIdx.x) * NCHUNK + ch] = h[threadIdx.x];
        g_smaxc[(b * MM + threadIdx.x) * NCHUNK + ch] = smax[threadIdx.x];
    }
}

// ---------------- sort pass 2: exclusive scan over [m][chunk] + segmax -------
__global__ void kscan() {
    const int b = blockIdx.x;
    const int t = threadIdx.x;                 // 0..1023
    int* h = g_hist + b * MM * NCHUNK;         // 8192 entries
    const int PER = (MM * NCHUNK) / 1024;      // 8
    int v[PER];
    int s = 0;
    #pragma unroll
    for (int k = 0; k < PER; k++) { v[k] = h[t * PER + k]; s += v[k]; }

    __shared__ int sh[1024];
    sh[t] = s; __syncthreads();
    for (int d = 1; d < 1024; d <<= 1) {       // Hillis-Steele inclusive
        int x = (t >= d) ? sh[t - d] : 0;
        __syncthreads();
        sh[t] += x;
        __syncthreads();
    }
    int run = t ? sh[t - 1] : 0;               // exclusive prefix
    #pragma unroll
    for (int k = 0; k < PER; k++) {
        int j = t * PER + k;
        h[j] = run;
        if ((j & (NCHUNK - 1)) == 0)
            g_mstart[b * MM + j / NCHUNK] = run;
        run += v[k];
    }

    if (t < MM) {                              // reduce per-chunk segmax
        const int* sc = g_smaxc + (b * MM + t) * NCHUNK;
        int mx = 0;
        #pragma unroll 8
        for (int c = 0; c < NCHUNK; c++) mx = max(mx, sc[c]);
        g_segmax[b * MM + t] = mx;
    }
}

// ---------------- sort pass 3: scatter via shared cursors ----------------
__global__ void kscatter(const int* __restrict__ inst) {
    const int b  = blockIdx.y;
    const int ch = blockIdx.x;
    __shared__ int cur[MM];
    if (threadIdx.x < MM)
        cur[threadIdx.x] = g_hist[(b * MM + threadIdx.x) * NCHUNK + ch];
    __syncthreads();

    const int base = ch * CH;
    unsigned short* so = g_sorder + b * NN;
    #pragma unroll
    for (int k = 0; k < CH / 256; k++) {
        int n = base + threadIdx.x + k * 256;
        int m = __ldg(inst + b * NN + n);
        int p = atomicAdd(&cur[m], 1);
        so[p] = (unsigned short)n;
    }
}

// ---------------- main accumulation kernel ----------------
// th = tanh(x/2): sigma(x)-0.5 = th/2; sigma(-x) = 0.5 - 0.5*th
// softplus(x) = -ln(sigma(-x))  -> batched product of sigma(-x) + one lg2
#define ELEM(VX, J) {                            \
    float x_  = (VX);                            \
    float th_ = tanha(0.5f * x_);                \
    sg[J] += 0.5f * th_;                         \
    sx[J] += x_;                                 \
    p[J]  *= fmaf(-0.5f, th_, 0.5f); }

__global__ void __launch_bounds__(128, 4) kmain(const float* __restrict__ mask) {
    // 1D grid remap: y = bid/148 so every SM hosts one block of each q-tile
    const int bid = blockIdx.x;            // 0..591
    const int y   = bid / 148;             // q-tile 0..3
    const int r   = bid % 148;
    const int b   = r / 37;                // batch
    const int xch = r % 37;                // row-chunk group
    const int lane = threadIdx.x & 31;
    const int w    = threadIdx.x >> 5;
    const int wc   = xch * 4 + w;          // 0..147
    const int RPW  = (NN + 147) / 148;     // 443 rows per warp
    int i  = wc * RPW;
    const int r1 = min(i + RPW, NN);

    const int qb = y * 128;
    const int q0 = qb + 4 * lane;
    const bool valid = (q0 < QQ);
    const int qc = valid ? q0 : qb;        // clamp into a touched sector

    // mstart table in warp registers
    const int* ms = g_mstart + b * MM;
    const int ms0 = ms[lane];
    const int ms1 = ms[lane + 32];

    unsigned bal0 = __ballot_sync(0xffffffffu, ms0 <= i);
    unsigned bal1 = __ballot_sync(0xffffffffu, ms1 <= i);
    int m = __popc(bal0) + __popc(bal1) - 1;   // last m with start <= i

    auto seg_end = [&](int mm) -> int {
        int nm = mm + 1;
        int lo = __shfl_sync(0xffffffffu, ms0, nm & 31);
        int hi = __shfl_sync(0xffffffffu, ms1, nm & 31);
        return (nm >= MM) ? NN : ((nm < 32) ? lo : hi);
    };

    const unsigned short* __restrict__ so = g_sorder + b * NN;
    const float* __restrict__ xb = mask + (size_t)b * NN * QQ + qc;

    float L[4] = {0.f, 0.f, 0.f, 0.f};

    while (i < r1) {
        while (seg_end(m) <= i) ++m;
        const int e   = min(r1, seg_end(m));
        const int s0i = i;
        float sx[4] = {0.f,0.f,0.f,0.f};
        float sg[4] = {0.f,0.f,0.f,0.f};
        float p[4]  = {1.f,1.f,1.f,1.f};

        // unroll-8 with front-batched LDG.128 gathers (4 KB in flight per warp)
        for (; i + 8 <= e; i += 8) {
            int ns[8];
            #pragma unroll
            for (int k = 0; k < 8; k++) ns[k] = so[i + k];
            float4 v[8];
            #pragma unroll
            for (int k = 0; k < 8; k++)
                v[k] = __ldg(reinterpret_cast<const float4*>(xb + (size_t)ns[k] * QQ));
            #pragma unroll
            for (int k = 0; k < 8; k++) {
                ELEM(v[k].x, 0); ELEM(v[k].y, 1); ELEM(v[k].z, 2); ELEM(v[k].w, 3);
            }
            #pragma unroll
            for (int j = 0; j < 4; j++) { L[j] += lg2a(p[j]); p[j] = 1.f; }
        }
        for (; i < e; ++i) {
            int ns = so[i];
            float4 v = __ldg(reinterpret_cast<const float4*>(xb + (size_t)ns * QQ));
            ELEM(v.x, 0); ELEM(v.y, 1); ELEM(v.z, 2); ELEM(v.w, 3);
        }
        #pragma unroll
        for (int j = 0; j < 4; j++) L[j] += lg2a(p[j]);

        // flush per-m sums (warp-uniform m; 512B coalesced atomic region)
        const int scnt = e - s0i;
        if (valid & (scnt > 0)) {
            float half = 0.5f * (float)scnt;
            float* aX = g_accX + ((b * MM + m) * QQ) + q0;
            float* aG = g_accG + ((b * MM + m) * QQ) + q0;
            #pragma unroll
            for (int j = 0; j < 4; j++) {
                atomicAdd(aX + j, sx[j]);
                atomicAdd(aG + j, sg[j] + half);
            }
        }
    }
    if (valid) {
        #pragma unroll
        for (int j = 0; j < 4; j++)
            atomicAdd(g_accL + b * QQ + q0 + j, L[j]);
    }
}

// ---------------- finalize: softmax + combine ----------------
__global__ void kfin(const float* __restrict__ cls, float* __restrict__ out) {
    const int q = blockIdx.x;
    const int b = blockIdx.y;
    const int m = threadIdx.x;   // 64 threads

    __shared__ float sl[CC];
    __shared__ float redG[MM];
    __shared__ float redX[MM];

    if (m < CC) sl[m] = cls[((size_t)b * QQ + q) * CC + m];

    const float X = g_accX[(b * MM + m) * QQ + q];
    const float G = g_accG[(b * MM + m) * QQ + q];
    redG[m] = G;
    redX[m] = X;
    __syncthreads();

    float mx = -1e30f;
    #pragma unroll
    for (int c = 0; c < CC; c++) mx = fmaxf(mx, sl[c]);
    float sum = 0.f;
    #pragma unroll
    for (int c = 0; c < CC; c++) sum += __expf(sl[c] - mx);

    float sigtot = 0.f;
    #pragma unroll
    for (int c = 0; c < MM; c++) sigtot += redG[c];

    const float Ltot = g_accL[b * QQ + q];      // sum log2(sigma(-x)) <= 0
    const float SPtot = -0.6931471805599453f * Ltot;

    const int st  = g_mstart[b * MM + m];
    const int en  = (m < MM - 1) ? g_mstart[b * MM + m + 1] : NN;
    const float cnt = (float)(en - st);

    const int segm = g_segmax[b * MM + m];
    const float prob = __expf(sl[segm] - mx) / sum;

    const float cmask  = (SPtot - X) * (1.0f / (float)NN);
    const float cclass = 1.0f - prob;
    const float cdice  = 1.0f - (2.0f * G + 1.0f) / (sigtot + cnt + 1.0f);

    out[((size_t)b * QQ + q) * MM + m] = cmask + cclass + cdice;
}

// ---------------- launcher ----------------
extern "C" void kernel_launch(void* const* d_in, const int* in_sizes, int n_in,
                              void* d_out, int out_size) {
    const float* mask = (const float*)d_in[0];   // [B,N,Q]
    const float* cls  = (const float*)d_in[1];   // [B,Q,C]
    const int*   inst = (const int*)d_in[2];     // [B,N]
    const int*   seg  = (const int*)d_in[3];     // [B,N]
    float*       out  = (float*)d_out;           // [B,Q,M]

    khist<<<dim3(NCHUNK, BB), 256>>>(inst, seg);
    kscan<<<BB, 1024>>>();
    kscatter<<<dim3(NCHUNK, BB), 256>>>(inst);
    kmain<<<592, 128>>>(mask);
    kfin<<<dim3(QQ, BB), MM>>>(cls, out);
}

// round 6
// speedup vs baseline: 1.0816x; 1.0816x over previous
#include <cuda_runtime.h>
#include <cstdint>

#define BB 4
#define NN 65536
#define QQ 400
#define CC 20
#define MM 64
#define CH 2048                  // rows per sort chunk
#define NCHUNK (NN / CH)         // 32 chunks per batch

// ---------------- device scratch (no mallocs allowed) ----------------
__device__ float g_accX[BB*MM*QQ];     // sum x per (b,m,q)
__device__ float g_accG[BB*MM*QQ];     // sum sigma-related per (b,m,q)
__device__ float g_accL[BB*QQ];        // sum log2(sigma(-x)) per (b,q)  [negative]
__device__ int   g_segmax[BB*MM];      // inst_seg
__device__ int   g_mstart[BB*MM];      // per-batch start offset of each m
__device__ int   g_hist[BB*MM*NCHUNK]; // [b][m][chunk] counts -> offsets
__device__ int   g_smaxc[BB*MM*NCHUNK];// [b][m][chunk] per-chunk seg max
__device__ unsigned short g_sorder[BB*NN]; // point indices grouped by m

// ---------------- fast approx ops ----------------
__device__ __forceinline__ float tanha(float x){ float r; asm("tanh.approx.f32 %0, %1;" : "=f"(r) : "f"(x)); return r; }
__device__ __forceinline__ float lg2a(float x){ float r; asm("lg2.approx.f32 %0, %1;" : "=f"(r) : "f"(x)); return r; }

// ---------------- sort pass 1: per-chunk histogram + segmax + zero accs ------
__global__ void khist(const int* __restrict__ inst, const int* __restrict__ seg) {
    const int b  = blockIdx.y;
    const int ch = blockIdx.x;
    __shared__ int h[MM];
    __shared__ int smax[MM];
    if (threadIdx.x < MM) { h[threadIdx.x] = 0; smax[threadIdx.x] = 0; }
    __syncthreads();

    // fused zeroing of accumulators (128 blocks x 256 thr, strided)
    const int gtid = (b * NCHUNK + ch) * 256 + threadIdx.x;   // 0..32767
    #pragma unroll
    for (int j = gtid; j < BB*MM*QQ; j += BB*NCHUNK*256) {
        g_accX[j] = 0.f;
        g_accG[j] = 0.f;
    }
    if (gtid < BB*QQ) g_accL[gtid] = 0.f;

    const int base = b * NN + ch * CH;
    #pragma unroll
    for (int k = 0; k < CH / 256; k++) {
        int n = base + threadIdx.x + k * 256;
        int m = __ldg(inst + n);
        int s = __ldg(seg + n);
        atomicAdd(&h[m], 1);
        atomicMax(&smax[m], s);
    }
    __syncthreads();
    if (threadIdx.x < MM) {
        g_hist [(b * MM + threadIdx.x) * NCHUNK + ch] = h[threadIdx.x];
        g_smaxc[(b * MM + threadIdx.x) * NCHUNK + ch] = smax[threadIdx.x];
    }
}

// ---------------- sort pass 2: exclusive scan over [m][chunk] + segmax -------
__global__ void kscan() {
    const int b = blockIdx.x;
    const int t = threadIdx.x;                 // 0..1023
    int* h = g_hist + b * MM * NCHUNK;         // 2048 entries
    int v0 = h[2*t], v1 = h[2*t + 1];
    __shared__ int sh[1024];
    sh[t] = v0 + v1; __syncthreads();
    for (int d = 1; d < 1024; d <<= 1) {       // Hillis-Steele inclusive
        int x = (t >= d) ? sh[t - d] : 0;
        __syncthreads();
        sh[t] += x;
        __syncthreads();
    }
    int pre = t ? sh[t - 1] : 0;               // exclusive
    h[2*t]     = pre;
    h[2*t + 1] = pre + v0;
    if (((2*t) & (NCHUNK - 1)) == 0)
        g_mstart[b * MM + (2*t) / NCHUNK] = pre;

    if (t < MM) {                              // reduce per-chunk segmax
        const int* sc = g_smaxc + (b * MM + t) * NCHUNK;
        int mx = 0;
        #pragma unroll
        for (int c = 0; c < NCHUNK; c++) mx = max(mx, sc[c]);
        g_segmax[b * MM + t] = mx;
    }
}

// ---------------- sort pass 3: scatter via shared cursors ----------------
__global__ void kscatter(const int* __restrict__ inst) {
    const int b  = blockIdx.y;
    const int ch = blockIdx.x;
    __shared__ int cur[MM];
    if (threadIdx.x < MM)
        cur[threadIdx.x] = g_hist[(b * MM + threadIdx.x) * NCHUNK + ch];
    __syncthreads();

    const int base = ch * CH;
    unsigned short* so = g_sorder + b * NN;
    #pragma unroll
    for (int k = 0; k < CH / 256; k++) {
        int n = base + threadIdx.x + k * 256;
        int m = __ldg(inst + b * NN + n);
        int p = atomicAdd(&cur[m], 1);
        so[p] = (unsigned short)n;
    }
}

// ---------------- main accumulation kernel ----------------
// th = tanh(x/2): sigma(x)-0.5 = th/2; sigma(-x) = 0.5 - 0.5*th
// softplus(x) = -ln(sigma(-x))  -> batched product of sigma(-x) + one lg2
#define ELEM(VX, J) {                            \
    float x_  = (VX);                            \
    float th_ = tanha(0.5f * x_);                \
    sg[J] += 0.5f * th_;                         \
    sx[J] += x_;                                 \
    p[J]  *= fmaf(-0.5f, th_, 0.5f); }

#define NWC 296                   // warp-chunks per (batch) row space
#define RPW 222                   // ceil(NN / NWC)

__global__ void __launch_bounds__(128, 8) kmain(const float* __restrict__ mask) {
    // 1184 blocks = 8 per SM, single wave. Decompose so each SM (bid%148)
    // hosts 2 blocks of every q-tile y: y = (bid/148)&3.
    const int bid = blockIdx.x;            // 0..1183
    const int wv  = bid / 148;             // 0..7
    const int s   = bid % 148;
    const int y   = wv & 3;                // q-tile 0..3
    const int idx = (wv >> 2) * 148 + s;   // 0..295
    const int b   = idx / 74;              // batch
    const int xch = idx % 74;              // row-chunk group
    const int lane = threadIdx.x & 31;
    const int w    = threadIdx.x >> 5;
    const int wc   = xch * 4 + w;          // 0..295
    int i  = wc * RPW;
    const int r1 = min(i + RPW, NN);

    const int qb = y * 128;
    const int q0 = qb + 4 * lane;
    const bool valid = (q0 < QQ);
    const int qc = valid ? q0 : qb;        // clamp into a touched sector

    // mstart table in warp registers
    const int* ms = g_mstart + b * MM;
    const int ms0 = ms[lane];
    const int ms1 = ms[lane + 32];

    unsigned bal0 = __ballot_sync(0xffffffffu, ms0 <= i);
    unsigned bal1 = __ballot_sync(0xffffffffu, ms1 <= i);
    int m = __popc(bal0) + __popc(bal1) - 1;   // last m with start <= i

    auto seg_end = [&](int mm) -> int {
        int nm = mm + 1;
        int lo = __shfl_sync(0xffffffffu, ms0, nm & 31);
        int hi = __shfl_sync(0xffffffffu, ms1, nm & 31);
        return (nm >= MM) ? NN : ((nm < 32) ? lo : hi);
    };

    const unsigned short* __restrict__ so = g_sorder + b * NN;
    const float* __restrict__ xb = mask + (size_t)b * NN * QQ + qc;

    float L[4] = {0.f, 0.f, 0.f, 0.f};

    while (i < r1) {
        while (seg_end(m) <= i) ++m;
        const int e   = min(r1, seg_end(m));
        const int s0i = i;
        float sx[4] = {0.f,0.f,0.f,0.f};
        float sg[4] = {0.f,0.f,0.f,0.f};
        float p[4]  = {1.f,1.f,1.f,1.f};

        // unroll-4 with front-batched LDG.128 gathers (2 KB in flight per warp)
        for (; i + 4 <= e; i += 4) {
            int ns0 = so[i], ns1 = so[i+1], ns2 = so[i+2], ns3 = so[i+3];
            float4 v0 = __ldg(reinterpret_cast<const float4*>(xb + (size_t)ns0 * QQ));
            float4 v1 = __ldg(reinterpret_cast<const float4*>(xb + (size_t)ns1 * QQ));
            float4 v2 = __ldg(reinterpret_cast<const float4*>(xb + (size_t)ns2 * QQ));
            float4 v3 = __ldg(reinterpret_cast<const float4*>(xb + (size_t)ns3 * QQ));
            ELEM(v0.x, 0); ELEM(v0.y, 1); ELEM(v0.z, 2); ELEM(v0.w, 3);
            ELEM(v1.x, 0); ELEM(v1.y, 1); ELEM(v1.z, 2); ELEM(v1.w, 3);
            ELEM(v2.x, 0); ELEM(v2.y, 1); ELEM(v2.z, 2); ELEM(v2.w, 3);
            ELEM(v3.x, 0); ELEM(v3.y, 1); ELEM(v3.z, 2); ELEM(v3.w, 3);
            #pragma unroll
            for (int j = 0; j < 4; j++) { L[j] += lg2a(p[j]); p[j] = 1.f; }
        }
        for (; i < e; ++i) {
            int ns = so[i];
            float4 v = __ldg(reinterpret_cast<const float4*>(xb + (size_t)ns * QQ));
            ELEM(v.x, 0); ELEM(v.y, 1); ELEM(v.z, 2); ELEM(v.w, 3);
        }
        #pragma unroll
        for (int j = 0; j < 4; j++) L[j] += lg2a(p[j]);

        // flush per-m sums (warp-uniform m; 512B coalesced atomic region)
        const int scnt = e - s0i;
        if (valid & (scnt > 0)) {
            float half = 0.5f * (float)scnt;
            float* aX = g_accX + ((b * MM + m) * QQ) + q0;
            float* aG = g_accG + ((b * MM + m) * QQ) + q0;
            #pragma unroll
            for (int j = 0; j < 4; j++) {
                atomicAdd(aX + j, sx[j]);
                atomicAdd(aG + j, sg[j] + half);
            }
        }
    }
    if (valid) {
        #pragma unroll
        for (int j = 0; j < 4; j++)
            atomicAdd(g_accL + b * QQ + q0 + j, L[j]);
    }
}

// ---------------- finalize: softmax + combine ----------------
__global__ void kfin(const float* __restrict__ cls, float* __restrict__ out) {
    const int q = blockIdx.x;
    const int b = blockIdx.y;
    const int m = threadIdx.x;   // 64 threads

    __shared__ float sl[CC];
    __shared__ float redG[MM];

    if (m < CC) sl[m] = cls[((size_t)b * QQ + q) * CC + m];

    const float X = g_accX[(b * MM + m) * QQ + q];
    const float G = g_accG[(b * MM + m) * QQ + q];
    redG[m] = G;
    __syncthreads();

    float mx = -1e30f;
    #pragma unroll
    for (int c = 0; c < CC; c++) mx = fmaxf(mx, sl[c]);
    float sum = 0.f;
    #pragma unroll
    for (int c = 0; c < CC; c++) sum += __expf(sl[c] - mx);

    float sigtot = 0.f;
    #pragma unroll
    for (int c = 0; c < MM; c++) sigtot += redG[c];

    const float Ltot = g_accL[b * QQ + q];      // sum log2(sigma(-x)) <= 0
    const float SPtot = -0.6931471805599453f * Ltot;

    const int st  = g_mstart[b * MM + m];
    const int en  = (m < MM - 1) ? g_mstart[b * MM + m + 1] : NN;
    const float cnt = (float)(en - st);

    const int segm = g_segmax[b * MM + m];
    const float prob = __expf(sl[segm] - mx) / sum;

    const float cmask  = (SPtot - X) * (1.0f / (float)NN);
    const float cclass = 1.0f - prob;
    const float cdice  = 1.0f - (2.0f * G + 1.0f) / (sigtot + cnt + 1.0f);

    out[((size_t)b * QQ + q) * MM + m] = cmask + cclass + cdice;
}

// ---------------- launcher ----------------
extern "C" void kernel_launch(void* const* d_in, const int* in_sizes, int n_in,
                              void* d_out, int out_size) {
    const float* mask = (const float*)d_in[0];   // [B,N,Q]
    const float* cls  = (const float*)d_in[1];   // [B,Q,C]
    const int*   inst = (const int*)d_in[2];     // [B,N]
    const int*   seg  = (const int*)d_in[3];     // [B,N]
    float*       out  = (float*)d_out;           // [B,Q,M]

    khist<<<dim3(NCHUNK, BB), 256>>>(inst, seg);
    kscan<<<BB, 1024>>>();
    kscatter<<<dim3(NCHUNK, BB), 256>>>(inst);
    kmain<<<1184, 128>>>(mask);
    kfin<<<dim3(QQ, BB), MM>>>(cls, out);
}

// round 10
// speedup vs baseline: 1.1768x; 1.0881x over previous
#include <cuda_runtime.h>
#include <cstdint>

#define BB 4
#define NN 65536
#define QQ 400
#define CC 20
#define MM 64
#define CH 1024                  // rows per sort chunk
#define NCHUNK (NN / CH)         // 64 chunks per batch

// ---------------- device scratch (no mallocs allowed) ----------------
__device__ float g_accX[BB*MM*QQ];     // sum x per (b,m,q)
__device__ float g_accG[BB*MM*QQ];     // sum sigma-related per (b,m,q)
__device__ float g_accL[BB*QQ];        // sum log2(sigma(-x)) per (b,q)  [negative]
__device__ int   g_segmax[BB*MM];      // inst_seg
__device__ int   g_mstart[BB*MM];      // per-batch start offset of each m
__device__ int   g_hist[BB*MM*NCHUNK]; // [b][m][chunk] counts -> offsets
__device__ int   g_smaxc[BB*MM*NCHUNK];// [b][m][chunk] per-chunk seg max
__device__ unsigned short g_sorder[BB*NN]; // point indices grouped by m

// ---------------- fast approx ops ----------------
__device__ __forceinline__ float tanha(float x){ float r; asm("tanh.approx.f32 %0, %1;" : "=f"(r) : "f"(x)); return r; }
__device__ __forceinline__ float lg2a(float x){ float r; asm("lg2.approx.f32 %0, %1;" : "=f"(r) : "f"(x)); return r; }

// ---------------- sort pass 1: per-chunk histogram + segmax + zero accs ------
__global__ void khist(const int* __restrict__ inst, const int* __restrict__ seg) {
    const int b  = blockIdx.y;
    const int ch = blockIdx.x;
    __shared__ int h[MM];
    __shared__ int smax[MM];
    if (threadIdx.x < MM) { h[threadIdx.x] = 0; smax[threadIdx.x] = 0; }
    __syncthreads();

    // fused zeroing of accumulators (256 blocks x 256 thr, 2-stride loop)
    const int gtid = (b * NCHUNK + ch) * 256 + threadIdx.x;   // 0..65535
    #pragma unroll
    for (int j = gtid; j < BB*MM*QQ; j += BB*NCHUNK*256) {
        g_accX[j] = 0.f;
        g_accG[j] = 0.f;
    }
    if (gtid < BB*QQ) g_accL[gtid] = 0.f;

    const int base = b * NN + ch * CH;
    #pragma unroll
    for (int k = 0; k < CH / 256; k++) {
        int n = base + threadIdx.x + k * 256;
        int m = __ldg(inst + n);
        int s = __ldg(seg + n);
        atomicAdd(&h[m], 1);
        atomicMax(&smax[m], s);
    }
    __syncthreads();
    if (threadIdx.x < MM) {
        g_hist [(b * MM + threadIdx.x) * NCHUNK + ch] = h[threadIdx.x];
        g_smaxc[(b * MM + threadIdx.x) * NCHUNK + ch] = smax[threadIdx.x];
    }
}

// ---------------- sort pass 2: shuffle-based exclusive scan + segmax ---------
__global__ void kscan() {
    const int b = blockIdx.x;
    const int t = threadIdx.x;                 // 0..1023
    const int lane = t & 31, wid = t >> 5;     // 32 warps
    int* h = g_hist + b * MM * NCHUNK;         // 4096 entries
    const int PER = (MM * NCHUNK) / 1024;      // 4
    int v[PER];
    int s = 0;
    #pragma unroll
    for (int k = 0; k < PER; k++) { v[k] = h[t * PER + k]; s += v[k]; }

    // warp inclusive scan of per-thread sums
    int inc = s;
    #pragma unroll
    for (int d = 1; d < 32; d <<= 1) {
        int x = __shfl_up_sync(0xffffffffu, inc, d);
        if (lane >= d) inc += x;
    }
    __shared__ int wtot[32];
    if (lane == 31) wtot[wid] = inc;
    __syncthreads();
    if (wid == 0) {                            // scan warp totals
        int w = wtot[lane];
        int wi = w;
        #pragma unroll
        for (int d = 1; d < 32; d <<= 1) {
            int x = __shfl_up_sync(0xffffffffu, wi, d);
            if (lane >= d) wi += x;
        }
        wtot[lane] = wi - w;                   // exclusive warp offset
    }
    __syncthreads();
    int run = wtot[wid] + inc - s;             // exclusive prefix for this thread

    #pragma unroll
    for (int k = 0; k < PER; k++) {
        int j = t * PER + k;
        h[j] = run;
        if ((j & (NCHUNK - 1)) == 0)
            g_mstart[b * MM + j / NCHUNK] = run;
        run += v[k];
    }

    if (t < MM) {                              // reduce per-chunk segmax
        const int* sc = g_smaxc + (b * MM + t) * NCHUNK;
        int mx = 0;
        #pragma unroll 8
        for (int c = 0; c < NCHUNK; c++) mx = max(mx, sc[c]);
        g_segmax[b * MM + t] = mx;
    }
}

// ---------------- sort pass 3: scatter via shared cursors ----------------
__global__ void kscatter(const int* __restrict__ inst) {
    const int b  = blockIdx.y;
    const int ch = blockIdx.x;
    __shared__ int cur[MM];
    if (threadIdx.x < MM)
        cur[threadIdx.x] = g_hist[(b * MM + threadIdx.x) * NCHUNK + ch];
    __syncthreads();

    const int base = ch * CH;
    unsigned short* so = g_sorder + b * NN;
    #pragma unroll
    for (int k = 0; k < CH / 256; k++) {
        int n = base + threadIdx.x + k * 256;
        int m = __ldg(inst + b * NN + n);
        int p = atomicAdd(&cur[m], 1);
        so[p] = (unsigned short)n;
    }
}

// ---------------- main accumulation kernel (R3 shape) ----------------
// th = tanh(x/2): sigma(x)-0.5 = th/2; sigma(-x) = 0.5 - 0.5*th
// softplus(x) = -ln(sigma(-x))  -> batched product of sigma(-x) + one lg2
#define ELEM_BODY(VX, SX, SG, PP) {              \
    float x_  = (VX);                            \
    float th_ = tanha(0.5f * x_);                \
    (SG) += 0.5f * th_;                          \
    (SX) += x_;                                  \
    (PP) *= fmaf(-0.5f, th_, 0.5f); }

__global__ void __launch_bounds__(128, 7) kmain(const float* __restrict__ mask) {
    const int b    = blockIdx.z;
    const int lane = threadIdx.x & 31;
    const int w    = threadIdx.x >> 5;
    const int wc   = blockIdx.x * 4 + w;            // 0..147
    const int RPW  = (NN + 147) / 148;              // 443 rows per warp
    int i  = wc * RPW;
    const int r1 = min(i + RPW, NN);

    const int qb = blockIdx.y * 64;
    const int q0 = qb + 2 * lane;
    const bool valid = (q0 < QQ);
    const int qc = valid ? q0 : qb;                 // clamp into a touched sector

    // mstart table in warp registers
    const int* ms = g_mstart + b * MM;
    const int ms0 = ms[lane];
    const int ms1 = ms[lane + 32];

    unsigned bal0 = __ballot_sync(0xffffffffu, ms0 <= i);
    unsigned bal1 = __ballot_sync(0xffffffffu, ms1 <= i);
    int m = __popc(bal0) + __popc(bal1) - 1;        // last m with start <= i

    auto seg_end = [&](int mm) -> int {
        int nm = mm + 1;
        int lo = __shfl_sync(0xffffffffu, ms0, nm & 31);
        int hi = __shfl_sync(0xffffffffu, ms1, nm & 31);
        return (nm >= MM) ? NN : ((nm < 32) ? lo : hi);
    };

    const unsigned short* __restrict__ so = g_sorder + b * NN;
    const float* __restrict__ xb = mask + (size_t)b * NN * QQ + qc;

    float L0 = 0.f, L1 = 0.f;

    while (i < r1) {
        while (seg_end(m) <= i) ++m;
        const int e   = min(r1, seg_end(m));
        const int s0i = i;
        float sx0 = 0.f, sx1 = 0.f, sg0 = 0.f, sg1 = 0.f;
        float p0 = 1.f, p1 = 1.f;

        // unroll-8: front-batched indices, 8 streaming gathers in flight
        for (; i + 8 <= e; i += 8) {
            int ns[8];
            #pragma unroll
            for (int k = 0; k < 8; k++) ns[k] = so[i + k];
            float2 v[8];
            #pragma unroll
            for (int k = 0; k < 8; k++)
                v[k] = __ldcs(reinterpret_cast<const float2*>(xb + (size_t)ns[k] * QQ));
            #pragma unroll
            for (int k = 0; k < 8; k++) {
                ELEM_BODY(v[k].x, sx0, sg0, p0);
                ELEM_BODY(v[k].y, sx1, sg1, p1);
            }
            L0 += lg2a(p0); p0 = 1.f;
            L1 += lg2a(p1); p1 = 1.f;
        }
        for (; i < e; ++i) {
            int ns = so[i];
            float2 v = __ldcs(reinterpret_cast<const float2*>(xb + (size_t)ns * QQ));
            ELEM_BODY(v.x, sx0, sg0, p0);
            ELEM_BODY(v.y, sx1, sg1, p1);
        }
        L0 += lg2a(p0);
        L1 += lg2a(p1);

        // flush per-m sums (warp-uniform m; 256B coalesced atomic region)
        const int scnt = e - s0i;
        if (valid & (scnt > 0)) {
            float half = 0.5f * (float)scnt;
            float* aX = g_accX + ((b * MM + m) * QQ);
            float* aG = g_accG + ((b * MM + m) * QQ);
            atomicAdd(aX + q0,     sx0);
            atomicAdd(aX + q0 + 1, sx1);
            atomicAdd(aG + q0,     sg0 + half);
            atomicAdd(aG + q0 + 1, sg1 + half);
        }
    }
    if (valid) {
        atomicAdd(g_accL + b * QQ + q0,     L0);
        atomicAdd(g_accL + b * QQ + q0 + 1, L1);
    }
}

// ---------------- finalize: softmax + combine ----------------
__global__ void kfin(const float* __restrict__ cls, float* __restrict__ out) {
    const int q = blockIdx.x;
    const int b = blockIdx.y;
    const int m = threadIdx.x;   // 64 threads

    __shared__ float sl[CC];
    __shared__ float redG[MM];

    if (m < CC) sl[m] = cls[((size_t)b * QQ + q) * CC + m];

    const float X = g_accX[(b * MM + m) * QQ + q];
    const float G = g_accG[(b * MM + m) * QQ + q];
    redG[m] = G;
    __syncthreads();

    float mx = -1e30f;
    #pragma unroll
    for (int c = 0; c < CC; c++) mx = fmaxf(mx, sl[c]);
    float sum = 0.f;
    #pragma unroll
    for (int c = 0; c < CC; c++) sum += __expf(sl[c] - mx);

    float sigtot = 0.f;
    #pragma unroll
    for (int c = 0; c < MM; c++) sigtot += redG[c];

    const float Ltot = g_accL[b * QQ + q];      // sum log2(sigma(-x)) <= 0
    const float SPtot = -0.6931471805599453f * Ltot;

    const int st  = g_mstart[b * MM + m];
    const int en  = (m < MM - 1) ? g_mstart[b * MM + m + 1] : NN;
    const float cnt = (float)(en - st);

    const int segm = g_segmax[b * MM + m];
    const float prob = __expf(sl[segm] - mx) / sum;

    const float cmask  = (SPtot - X) * (1.0f / (float)NN);
    const float cclass = 1.0f - prob;
    const float cdice  = 1.0f - (2.0f * G + 1.0f) / (sigtot + cnt + 1.0f);

    out[((size_t)b * QQ + q) * MM + m] = cmask + cclass + cdice;
}

// ---------------- launcher ----------------
extern "C" void kernel_launch(void* const* d_in, const int* in_sizes, int n_in,
                              void* d_out, int out_size) {
    const float* mask = (const float*)d_in[0];   // [B,N,Q]
    const float* cls  = (const float*)d_in[1];   // [B,Q,C]
    const int*   inst = (const int*)d_in[2];     // [B,N]
    const int*   seg  = (const int*)d_in[3];     // [B,N]
    float*       out  = (float*)d_out;           // [B,Q,M]

    khist<<<dim3(NCHUNK, BB), 256>>>(inst, seg);
    kscan<<<BB, 1024>>>();
    kscatter<<<dim3(NCHUNK, BB), 256>>>(inst);
    kmain<<<dim3(37, 7, BB), 128>>>(mask);
    kfin<<<dim3(QQ, BB), MM>>>(cls, out);
}